// round 7
// baseline (speedup 1.0000x reference)
#include <cuda_runtime.h>
#include <cstdint>

// Problem constants (fixed by the reference: B=8, N=16384, RATIO=0.5, C=128)
#define BB 8
#define NN 16384
#define NPOINT 8192
#define CC 128
#define T 256                  // threads per CTA (8 warps)
#define CSIZE 16               // CTAs per batch (nonportable cluster size)
#define NC (NN / CSIZE)        // 1024 points per CTA
#define NWARP (T / 32)         // 8 warps
#define PPT (NC / T)           // 4 points per thread
#define NSLOT (CSIZE * NWARP)  // 128 cross slots per buffer

typedef unsigned long long u64;
typedef unsigned int u32;

// Scratch: selected indices per batch (device global — no allocation allowed)
__device__ int g_idx[BB * NPOINT];

// ---------------------------------------------------------------------------
// helpers
// ---------------------------------------------------------------------------
__device__ __forceinline__ u32 smem_u32(const void* p) {
    return (u32)__cvta_generic_to_shared(p);
}
__device__ __forceinline__ void vld64x2(u32 a, u64& v0, u64& v1) {
    asm volatile("ld.volatile.shared.v2.u64 {%0, %1}, [%2];"
                 : "=l"(v0), "=l"(v1) : "r"(a) : "memory");
}
__device__ __forceinline__ u32 mapa_rank(u32 laddr, u32 rank) {
    u32 ra;
    asm volatile("mapa.shared::cluster.u32 %0, %1, %2;" : "=r"(ra) : "r"(laddr), "r"(rank));
    return ra;
}
__device__ __forceinline__ void st_cluster64(u32 raddr, u64 v) {
    asm volatile("st.relaxed.cluster.shared::cluster.b64 [%0], %1;" :: "r"(raddr), "l"(v) : "memory");
}

// ---------------------------------------------------------------------------
// FPS: 16-CTA cluster per batch (nonportable size, set at launch), 256
// threads/CTA, 4 points/thread (registers). Per-point distance arithmetic is
// the VERBATIM scalar expression from the rel_err==0.0 kernels — do not touch.
//
// ONE-STAGE all-to-all reduction per iteration:
//   thread:  pairwise argmax tree over 4 points (prefer-left = lower index
//            on ties, exact jnp.argmax semantics)
//   warp:    2x REDUX -> warp key (held by EVERY lane)
//   all-to-all: lanes 0..15 each issue ONE remote store of the warp key to
//            rank=lane, slot [rank*NWARP+wid] — one SIMT instruction puts all
//            16 remote stores in flight simultaneously.
//   every warp: polls all 128 tagged slots, lane L reads the contiguous 32B
//            {4L..4L+3} with two ld.volatile.v2.u64; local u64 max, then
//            2x REDUX -> f.
// Keys: (dist_bits<<32) | (tag<<16) | (NN-1-idx); within one iteration all
// tags are equal so u64 max == (max dist, then first index) — jnp.argmax
// tie-breaking. Tags self-synchronize the spin; double buffering (j&1)
// prevents overwrite races: a warp writes buffer (j+2)&1 only after passing
// poll j+1, which required every warp of every rank to have posted j+1,
// which required them to have finished reading buffer j&1.
// ---------------------------------------------------------------------------
extern "C" __global__ void __launch_bounds__(T, 1)
fps_kernel(const float* __restrict__ xyz)
{
    const int blk  = blockIdx.x;
    const int b    = blk / CSIZE;
    const u32 rank = (u32)(blk % CSIZE);   // == %cluster_ctarank (1D clusters)
    const int tid  = threadIdx.x;
    const int wid  = tid >> 5;
    const int lane = tid & 31;

    extern __shared__ float smem[];
    float* sx = smem;                               // [NN]
    float* sy = smem + NN;                          // [NN]
    float* sz = smem + 2 * NN;                      // [NN]
    u64* crossSlots = (u64*)(smem + 3 * NN);        // [2][NSLOT], 16B-aligned

    const float* __restrict__ p = xyz + (size_t)b * NN * 3;

    // Full xyz table in smem (centroid lookup must cover all 16384 points)
    for (int i = tid; i < NN; i += T) {
        sx[i] = p[3 * i + 0];
        sy[i] = p[3 * i + 1];
        sz[i] = p[3 * i + 2];
    }
    // zero slots: 2*NSLOT == 256 == T, one per thread
    crossSlots[tid] = 0ull;
    __syncthreads();
    // all CTAs' slots must be zeroed before any peer's first DSMEM store
    asm volatile("barrier.cluster.arrive.aligned;" ::: "memory");
    asm volatile("barrier.cluster.wait.aligned;"   ::: "memory");

    // Own 4 points, register-resident: i_k = base + k*T (k ascending => index ascending)
    const int base = (int)rank * NC + tid;
    float X[PPT], Y[PPT], Z[PPT], D[PPT];
#pragma unroll
    for (int k = 0; k < PPT; k++) {
        const int i = base + k * T;
        X[k] = sx[i]; Y[k] = sy[i]; Z[k] = sz[i];
        D[k] = 1e10f;
    }

    const u32 csBase = smem_u32(crossSlots);

    // Per-lane peer address: lanes 0..15 target rank=lane, slot [rank*NWARP+wid].
    const u32 peerAddr = mapa_rank(csBase, (u32)(lane & (CSIZE - 1)))
                       + (u32)(((int)rank * NWARP + wid) * 8);

    // Each lane polls the contiguous 4-slot group {4L..4L+3} (32B, 2x v2).
    const u32 pollAddr = csBase + (u32)(lane * 32);

    int f = 0;   // init_far = 0 (reference)
    int* __restrict__ idxo = g_idx + b * NPOINT;

    for (int j = 0; j < NPOINT; j++) {
        const u32 tag = (u32)(j + 1);   // 1..8192 (14 bits)
        const u32 bufOff = (u32)((j & 1) * (NSLOT * 8));

        if (rank == 0 && tid == 0) idxo[j] = f;  // scan emits farthest BEFORE update

        // distance update — IDENTICAL source expression to prior passing rounds
        const float cx = sx[f], cy = sy[f], cz = sz[f];
        float nd[PPT];
#pragma unroll
        for (int k = 0; k < PPT; k++) {
            float dx = X[k] - cx;
            float dy = Y[k] - cy;
            float dz = Z[k] - cz;
            float d = dx * dx + dy * dy + dz * dz;
            float v = fminf(D[k], d);
            D[k] = v;
            nd[k] = v;
        }

        // thread-level argmax tree over 4 values; prefer-left keeps lowest k
        // (k ascending == global index ascending): first-index tie-break.
        float bd[PPT]; int bk[PPT];
#pragma unroll
        for (int k = 0; k < PPT; k++) { bd[k] = nd[k]; bk[k] = k; }
#pragma unroll
        for (int s = PPT / 2; s > 0; s >>= 1) {
#pragma unroll
            for (int k = 0; k < PPT; k++) {
                if (k < s) {
                    if (bd[k + s] > bd[k]) { bd[k] = bd[k + s]; bk[k] = bk[k + s]; }
                }
            }
        }
        const float best = bd[0];
        const int   bi   = base + bk[0] * T;

        // warp-level: max dist bits, then max of (NN-1-idx) among maxima
        const u32 ub  = __float_as_uint(best);          // dist >= 0: bit order == float order
        const u32 wm  = __reduce_max_sync(0xFFFFFFFFu, ub);
        const u32 cnd = (ub == wm) ? (u32)(NN - 1 - bi) : 0u;
        const u32 wi  = __reduce_max_sync(0xFFFFFFFFu, cnd);

        // all-to-all: lanes 0..15 each fire ONE remote store (parallel fan-out)
        const u64 wkey = ((u64)wm << 32) | ((u64)tag << 16) | (u64)wi;
        if (lane < CSIZE)
            st_cluster64(peerAddr + bufOff, wkey);

        // every warp: poll all 128 slots (32B per lane), then reduce
        u64 k0, k1, k2, k3;
        do {
            vld64x2(pollAddr + bufOff,      k0, k1);
            vld64x2(pollAddr + bufOff + 16, k2, k3);
        } while (__any_sync(0xFFFFFFFFu,
                 ((((u32)k0 >> 16) ^ tag) | (((u32)k1 >> 16) ^ tag) |
                  (((u32)k2 >> 16) ^ tag) | (((u32)k3 >> 16) ^ tag)) != 0u));

        const u64 a01 = (k1 > k0) ? k1 : k0;  // tags equal: dist, then first-index
        const u64 a23 = (k3 > k2) ? k3 : k2;
        const u64 k   = (a23 > a01) ? a23 : a01;
        const u32 hi = (u32)(k >> 32);
        const u32 lo = (u32)k;
        const u32 M1 = __reduce_max_sync(0xFFFFFFFFu, hi);
        const u32 C1 = (hi == M1) ? lo : 0u;  // tag bits identical across lanes
        const u32 M2 = __reduce_max_sync(0xFFFFFFFFu, C1);
        f = NN - 1 - (int)(M2 & 0x3FFFu);
    }
}

// ---------------------------------------------------------------------------
// Gather feats: out[b][c][m] = feats[b][c][ idx[b][m] ]
// ---------------------------------------------------------------------------
extern "C" __global__ void gather_feats_kernel(const float* __restrict__ feats,
                                               float* __restrict__ out) {
    long long l = (long long)blockIdx.x * blockDim.x + threadIdx.x;
    const long long total = (long long)BB * CC * NPOINT;
    if (l >= total) return;
    int m = (int)(l % NPOINT);
    long long bc = l / NPOINT;          // b*C + c
    int b = (int)(bc / CC);
    int i = g_idx[b * NPOINT + m];
    out[l] = feats[bc * NN + i];
}

// ---------------------------------------------------------------------------
// Gather xyz: out[b][m][d] = xyz[b][idx[b][m]][d]
// ---------------------------------------------------------------------------
extern "C" __global__ void gather_xyz_kernel(const float* __restrict__ xyz,
                                             float* __restrict__ out) {
    int l = blockIdx.x * blockDim.x + threadIdx.x;   // over B*NPOINT
    if (l >= BB * NPOINT) return;
    int b = l / NPOINT;
    int i = g_idx[l];
    const float* src = xyz + ((size_t)b * NN + i) * 3;
    float* dst = out + (size_t)l * 3;
    dst[0] = src[0];
    dst[1] = src[1];
    dst[2] = src[2];
}

// ---------------------------------------------------------------------------
extern "C" void kernel_launch(void* const* d_in, const int* in_sizes, int n_in,
                              void* d_out, int out_size) {
    // Identify inputs by element count (robust to ordering):
    // feats = 8*128*16384 = 16777216, xyz = 8*16384*3 = 393216
    const float* feats = (const float*)d_in[0];
    const float* xyz   = (const float*)d_in[1];
    if (in_sizes[0] == BB * NN * 3) {
        xyz   = (const float*)d_in[0];
        feats = (const float*)d_in[1];
    }

    float* out = (float*)d_out;
    float* out_feats = out;                                   // B*C*NPOINT
    float* out_xyz   = out + (size_t)BB * CC * NPOINT;        // B*NPOINT*3

    const size_t smem = (size_t)3 * NN * sizeof(float)
                      + 2 * NSLOT * sizeof(u64);
    cudaFuncSetAttribute(fps_kernel,
                         cudaFuncAttributeMaxDynamicSharedMemorySize,
                         (int)smem);
    cudaFuncSetAttribute(fps_kernel,
                         cudaFuncAttributeNonPortableClusterSizeAllowed, 1);

    // Launch FPS with a 16-CTA cluster (nonportable size) via launch attrs.
    cudaLaunchConfig_t cfg = {};
    cfg.gridDim = dim3(BB * CSIZE, 1, 1);
    cfg.blockDim = dim3(T, 1, 1);
    cfg.dynamicSmemBytes = smem;
    cfg.stream = 0;  // legacy default stream (same one prior rounds captured on)
    cudaLaunchAttribute attrs[1];
    attrs[0].id = cudaLaunchAttributeClusterDimension;
    attrs[0].val.clusterDim = {CSIZE, 1, 1};
    cfg.attrs = attrs;
    cfg.numAttrs = 1;
    cudaLaunchKernelEx(&cfg, fps_kernel, xyz);

    const long long feat_total = (long long)BB * CC * NPOINT;
    int gb = (int)((feat_total + 255) / 256);
    gather_feats_kernel<<<gb, 256>>>(feats, out_feats);

    int xb = (BB * NPOINT + 255) / 256;
    gather_xyz_kernel<<<xb, 256>>>(xyz, out_xyz);
}

// round 8
// speedup vs baseline: 1.1596x; 1.1596x over previous
#include <cuda_runtime.h>
#include <cstdint>

// Problem constants (fixed by the reference: B=8, N=16384, RATIO=0.5, C=128)
#define BB 8
#define NN 16384
#define NPOINT 8192
#define CC 128
#define T 256                // threads per CTA (8 warps)
#define CSIZE 8              // CTAs per batch (cluster size) — 16 regressed 3.5x (R7)
#define NC (NN / CSIZE)      // 2048 points per CTA
#define NWARP (T / 32)       // 8 warps
#define PPT (NC / T)         // 8 points per thread
#define NSLOT (CSIZE * NWARP)  // 64 cross slots per buffer

typedef unsigned long long u64;
typedef unsigned int u32;

// Scratch: selected indices per batch (device global — no allocation allowed)
__device__ int g_idx[BB * NPOINT];

// ---------------------------------------------------------------------------
// helpers
// ---------------------------------------------------------------------------
__device__ __forceinline__ u32 smem_u32(const void* p) {
    return (u32)__cvta_generic_to_shared(p);
}
__device__ __forceinline__ void vld64x2(u32 a, u64& v0, u64& v1) {
    asm volatile("ld.volatile.shared.v2.u64 {%0, %1}, [%2];"
                 : "=l"(v0), "=l"(v1) : "r"(a) : "memory");
}
__device__ __forceinline__ u32 mapa_rank(u32 laddr, u32 rank) {
    u32 ra;
    asm volatile("mapa.shared::cluster.u32 %0, %1, %2;" : "=r"(ra) : "r"(laddr), "r"(rank));
    return ra;
}
__device__ __forceinline__ void st_cluster64(u32 raddr, u64 v) {
    asm volatile("st.relaxed.cluster.shared::cluster.b64 [%0], %1;" :: "r"(raddr), "l"(v) : "memory");
}

// ---------------------------------------------------------------------------
// FPS: 8-CTA cluster per batch, 256 threads/CTA, 8 points/thread (registers).
// Per-point distance arithmetic is the VERBATIM scalar expression from the
// rel_err==0.0 kernels (rounds 1/3/4/5/6) — do not touch.
//
// ONE-STAGE all-to-all reduction per iteration (R6 structure):
//   thread:  pairwise argmax tree over 8 points (prefer-left = lower index
//            on ties, exact jnp.argmax semantics)
//   warp:    2x REDUX -> warp key (held by EVERY lane)
//   all-to-all: lanes 0..7 each issue ONE remote store of the warp key to
//            rank=lane, slot [rank*NWARP+wid] (parallel fan-out)
//   every warp: each lane spins ONLY on its own contiguous 16B slot pair
//            {2L,2L+1} (R8: divergent per-lane spin, no vote in the loop —
//            ready lanes stop issuing LDS, freeing the smem port for the
//            incoming producer-pays DSMEM stores); reconverges at REDUX.
// Keys: (dist_bits<<32) | (tag<<16) | (NN-1-idx); within one iteration all
// tags are equal so u64 max == (max dist, then first index) — jnp.argmax
// tie-breaking. Tags self-synchronize the spin; double buffering (j&1)
// prevents overwrite races: a warp writes buffer (j+2)&1 only after passing
// poll j+1, which required every warp of every rank to have posted j+1,
// which required them to have finished reading buffer j&1.
//
// SMEM layout (R8): xy as float2 (one LDS.64 for centroid xy) + z plane.
// ---------------------------------------------------------------------------
extern "C" __global__ void __launch_bounds__(T, 1) __cluster_dims__(CSIZE, 1, 1)
fps_kernel(const float* __restrict__ xyz)
{
    const int blk  = blockIdx.x;
    const int b    = blk / CSIZE;
    const u32 rank = (u32)(blk % CSIZE);
    const int tid  = threadIdx.x;
    const int wid  = tid >> 5;
    const int lane = tid & 31;

    extern __shared__ float smem[];
    float2* sxy = (float2*)smem;                    // [NN]  (128 KB)
    float*  sz  = smem + 2 * NN;                    // [NN]  (64 KB)
    u64* crossSlots = (u64*)(smem + 3 * NN);        // [2][NSLOT], 16B-aligned

    const float* __restrict__ p = xyz + (size_t)b * NN * 3;

    // Full xyz table in smem (centroid lookup must cover all 16384 points)
    for (int i = tid; i < NN; i += T) {
        float x = p[3 * i + 0];
        float y = p[3 * i + 1];
        float z = p[3 * i + 2];
        sxy[i] = make_float2(x, y);
        sz[i]  = z;
    }
    if (tid < 2 * NSLOT) crossSlots[tid] = 0ull;
    __syncthreads();
    // all CTAs' slots must be zeroed before any peer's first DSMEM store
    asm volatile("barrier.cluster.arrive.aligned;" ::: "memory");
    asm volatile("barrier.cluster.wait.aligned;"   ::: "memory");

    // Own 8 points, register-resident: i_k = base + k*T (k ascending => index ascending)
    const int base = (int)rank * NC + tid;
    float X[PPT], Y[PPT], Z[PPT], D[PPT];
#pragma unroll
    for (int k = 0; k < PPT; k++) {
        const int i = base + k * T;
        float2 xy = sxy[i];
        X[k] = xy.x; Y[k] = xy.y; Z[k] = sz[i];
        D[k] = 1e10f;
    }

    const u32 csBase = smem_u32(crossSlots);

    // Per-lane peer address: lanes 0..7 target rank=lane, slot [rank*NWARP+wid].
    const u32 peerAddr = mapa_rank(csBase, (u32)(lane & (CSIZE - 1)))
                       + (u32)(((int)rank * NWARP + wid) * 8);

    // Each lane polls the contiguous slot pair {2*lane, 2*lane+1} (16B, v2).
    const u32 pollAddr = csBase + (u32)(lane * 16);

    int f = 0;   // init_far = 0 (reference)
    int* __restrict__ idxo = g_idx + b * NPOINT;

    for (int j = 0; j < NPOINT; j++) {
        const u32 tag = (u32)(j + 1);   // 1..8192 (14 bits)
        const u32 bufOff = (u32)((j & 1) * (NSLOT * 8));

        if (rank == 0 && tid == 0) idxo[j] = f;  // scan emits farthest BEFORE update

        // distance update — IDENTICAL source expression to prior passing rounds
        const float2 cxy = sxy[f];
        const float cz = sz[f];
        const float cx = cxy.x, cy = cxy.y;
        float nd[PPT];
#pragma unroll
        for (int k = 0; k < PPT; k++) {
            float dx = X[k] - cx;
            float dy = Y[k] - cy;
            float dz = Z[k] - cz;
            float d = dx * dx + dy * dy + dz * dz;
            float v = fminf(D[k], d);
            D[k] = v;
            nd[k] = v;
        }

        // thread-level argmax tree over 8 values; prefer-left keeps lowest k
        // (k ascending == global index ascending): first-index tie-break.
        float bd[PPT]; int bk[PPT];
#pragma unroll
        for (int k = 0; k < PPT; k++) { bd[k] = nd[k]; bk[k] = k; }
#pragma unroll
        for (int s = PPT / 2; s > 0; s >>= 1) {
#pragma unroll
            for (int k = 0; k < PPT; k++) {
                if (k < s) {
                    if (bd[k + s] > bd[k]) { bd[k] = bd[k + s]; bk[k] = bk[k + s]; }
                }
            }
        }
        const float best = bd[0];
        const int   bi   = base + bk[0] * T;

        // warp-level: max dist bits, then max of (NN-1-idx) among maxima
        const u32 ub  = __float_as_uint(best);          // dist >= 0: bit order == float order
        const u32 wm  = __reduce_max_sync(0xFFFFFFFFu, ub);
        const u32 cnd = (ub == wm) ? (u32)(NN - 1 - bi) : 0u;
        const u32 wi  = __reduce_max_sync(0xFFFFFFFFu, cnd);

        // all-to-all: lanes 0..7 each fire ONE remote store (parallel fan-out)
        const u64 wkey = ((u64)wm << 32) | ((u64)tag << 16) | (u64)wi;
        if (lane < CSIZE)
            st_cluster64(peerAddr + bufOff, wkey);

        // per-lane divergent spin on own 16B pair; reconverge at REDUX below
        u64 k0, k1;
        do {
            vld64x2(pollAddr + bufOff, k0, k1);
        } while (((((u32)k0 >> 16) ^ tag) | (((u32)k1 >> 16) ^ tag)) != 0u);

        const u64 k  = (k1 > k0) ? k1 : k0;   // tags equal: dist, then first-index
        const u32 hi = (u32)(k >> 32);
        const u32 lo = (u32)k;
        const u32 M1 = __reduce_max_sync(0xFFFFFFFFu, hi);
        const u32 C1 = (hi == M1) ? lo : 0u;  // tag bits identical across lanes
        const u32 M2 = __reduce_max_sync(0xFFFFFFFFu, C1);
        f = NN - 1 - (int)(M2 & 0x3FFFu);
    }
}

// ---------------------------------------------------------------------------
// Gather feats: out[b][c][m] = feats[b][c][ idx[b][m] ]
// ---------------------------------------------------------------------------
extern "C" __global__ void gather_feats_kernel(const float* __restrict__ feats,
                                               float* __restrict__ out) {
    long long l = (long long)blockIdx.x * blockDim.x + threadIdx.x;
    const long long total = (long long)BB * CC * NPOINT;
    if (l >= total) return;
    int m = (int)(l % NPOINT);
    long long bc = l / NPOINT;          // b*C + c
    int b = (int)(bc / CC);
    int i = g_idx[b * NPOINT + m];
    out[l] = feats[bc * NN + i];
}

// ---------------------------------------------------------------------------
// Gather xyz: out[b][m][d] = xyz[b][idx[b][m]][d]
// ---------------------------------------------------------------------------
extern "C" __global__ void gather_xyz_kernel(const float* __restrict__ xyz,
                                             float* __restrict__ out) {
    int l = blockIdx.x * blockDim.x + threadIdx.x;   // over B*NPOINT
    if (l >= BB * NPOINT) return;
    int b = l / NPOINT;
    int i = g_idx[l];
    const float* src = xyz + ((size_t)b * NN + i) * 3;
    float* dst = out + (size_t)l * 3;
    dst[0] = src[0];
    dst[1] = src[1];
    dst[2] = src[2];
}

// ---------------------------------------------------------------------------
extern "C" void kernel_launch(void* const* d_in, const int* in_sizes, int n_in,
                              void* d_out, int out_size) {
    // Identify inputs by element count (robust to ordering):
    // feats = 8*128*16384 = 16777216, xyz = 8*16384*3 = 393216
    const float* feats = (const float*)d_in[0];
    const float* xyz   = (const float*)d_in[1];
    if (in_sizes[0] == BB * NN * 3) {
        xyz   = (const float*)d_in[0];
        feats = (const float*)d_in[1];
    }

    float* out = (float*)d_out;
    float* out_feats = out;                                   // B*C*NPOINT
    float* out_xyz   = out + (size_t)BB * CC * NPOINT;        // B*NPOINT*3

    const size_t smem = (size_t)3 * NN * sizeof(float)
                      + 2 * NSLOT * sizeof(u64);
    cudaFuncSetAttribute(fps_kernel,
                         cudaFuncAttributeMaxDynamicSharedMemorySize,
                         (int)smem);

    fps_kernel<<<BB * CSIZE, T, smem>>>(xyz);

    const long long feat_total = (long long)BB * CC * NPOINT;
    int gb = (int)((feat_total + 255) / 256);
    gather_feats_kernel<<<gb, 256>>>(feats, out_feats);

    int xb = (BB * NPOINT + 255) / 256;
    gather_xyz_kernel<<<xb, 256>>>(xyz, out_xyz);
}

// round 9
// speedup vs baseline: 3.5096x; 3.0264x over previous
#include <cuda_runtime.h>
#include <cstdint>

// Problem constants (fixed by the reference: B=8, N=16384, RATIO=0.5, C=128)
#define BB 8
#define NN 16384
#define NPOINT 8192
#define CC 128
#define T 256                // threads per CTA (8 warps)
#define CSIZE 8              // CTAs per batch — 16 regressed 3.5x (R7)
#define NC (NN / CSIZE)      // 2048 points per CTA
#define NWARP (T / 32)       // 8 warps
#define PPT (NC / T)         // 8 points per thread
#define NSLOT (CSIZE * NWARP)  // 64 cross slots per buffer

typedef unsigned long long u64;
typedef unsigned int u32;

// Scratch: selected indices per batch (device global — no allocation allowed)
__device__ int g_idx[BB * NPOINT];

// ---------------------------------------------------------------------------
// helpers
// ---------------------------------------------------------------------------
__device__ __forceinline__ u32 smem_u32(const void* p) {
    return (u32)__cvta_generic_to_shared(p);
}
__device__ __forceinline__ void vld64x2(u32 a, u64& v0, u64& v1) {
    asm volatile("ld.volatile.shared.v2.u64 {%0, %1}, [%2];"
                 : "=l"(v0), "=l"(v1) : "r"(a) : "memory");
}
__device__ __forceinline__ u32 mapa_rank(u32 laddr, u32 rank) {
    u32 ra;
    asm volatile("mapa.shared::cluster.u32 %0, %1, %2;" : "=r"(ra) : "r"(laddr), "r"(rank));
    return ra;
}
__device__ __forceinline__ void st_cluster64(u32 raddr, u64 v) {
    asm volatile("st.relaxed.cluster.shared::cluster.b64 [%0], %1;" :: "r"(raddr), "l"(v) : "memory");
}

// ---------------------------------------------------------------------------
// FPS: 8-CTA cluster per batch, 256 threads/CTA, 8 points/thread (registers).
// EXACT R6 structure (best measured: 2704us) — the only change vs R6 is the
// float2 sxy SMEM layout (centroid xy in one LDS.64).
//
// Per-point distance arithmetic is the VERBATIM scalar expression from the
// rel_err==0.0 kernels — do not touch (hand-reassociation flipped near-tie
// selections in R2).
//
// ONE-STAGE all-to-all reduction per iteration:
//   thread:  pairwise argmax tree over 8 points (prefer-left = lower index
//            on ties, exact jnp.argmax semantics)
//   warp:    2x REDUX -> warp key (held by EVERY lane)
//   all-to-all: lanes 0..7 each issue ONE remote store of the warp key to
//            rank=lane, slot [rank*NWARP+wid] (parallel fan-out)
//   every warp: CONVERGENT VOTED poll (R8's divergent per-lane spin
//            regressed 3x — the __any_sync vote keeps the warp convergent
//            and the spin cheap); lane L reads pair {2L,2L+1} via v2.u64;
//            local u64 max; 2x REDUX -> f.
// Keys: (dist_bits<<32) | (tag<<16) | (NN-1-idx); within one iteration all
// tags are equal so u64 max == (max dist, then first index) — jnp.argmax
// tie-breaking. Tags self-synchronize the spin; double buffering (j&1)
// prevents overwrite races: a warp writes buffer (j+2)&1 only after passing
// poll j+1, which required every warp of every rank to have posted j+1,
// which required them to have finished reading buffer j&1.
// ---------------------------------------------------------------------------
extern "C" __global__ void __launch_bounds__(T, 1) __cluster_dims__(CSIZE, 1, 1)
fps_kernel(const float* __restrict__ xyz)
{
    const int blk  = blockIdx.x;
    const int b    = blk / CSIZE;
    const u32 rank = (u32)(blk % CSIZE);
    const int tid  = threadIdx.x;
    const int wid  = tid >> 5;
    const int lane = tid & 31;

    extern __shared__ float smem[];
    float2* sxy = (float2*)smem;                    // [NN]  (128 KB)
    float*  sz  = smem + 2 * NN;                    // [NN]  (64 KB)
    u64* crossSlots = (u64*)(smem + 3 * NN);        // [2][NSLOT], 16B-aligned

    const float* __restrict__ p = xyz + (size_t)b * NN * 3;

    // Full xyz table in smem (centroid lookup must cover all 16384 points)
    for (int i = tid; i < NN; i += T) {
        float x = p[3 * i + 0];
        float y = p[3 * i + 1];
        float z = p[3 * i + 2];
        sxy[i] = make_float2(x, y);
        sz[i]  = z;
    }
    if (tid < 2 * NSLOT) crossSlots[tid] = 0ull;
    __syncthreads();
    // all CTAs' slots must be zeroed before any peer's first DSMEM store
    asm volatile("barrier.cluster.arrive.aligned;" ::: "memory");
    asm volatile("barrier.cluster.wait.aligned;"   ::: "memory");

    // Own 8 points, register-resident: i_k = base + k*T (k ascending => index ascending)
    const int base = (int)rank * NC + tid;
    float X[PPT], Y[PPT], Z[PPT], D[PPT];
#pragma unroll
    for (int k = 0; k < PPT; k++) {
        const int i = base + k * T;
        float2 xy = sxy[i];
        X[k] = xy.x; Y[k] = xy.y; Z[k] = sz[i];
        D[k] = 1e10f;
    }

    const u32 csBase = smem_u32(crossSlots);

    // Per-lane peer address: lanes 0..7 target rank=lane, slot [rank*NWARP+wid].
    const u32 peerAddr = mapa_rank(csBase, (u32)(lane & (CSIZE - 1)))
                       + (u32)(((int)rank * NWARP + wid) * 8);

    // Each lane polls the contiguous slot pair {2*lane, 2*lane+1} (16B, v2).
    const u32 pollAddr = csBase + (u32)(lane * 16);

    int f = 0;   // init_far = 0 (reference)
    int* __restrict__ idxo = g_idx + b * NPOINT;

    for (int j = 0; j < NPOINT; j++) {
        const u32 tag = (u32)(j + 1);   // 1..8192 (14 bits)
        const u32 bufOff = (u32)((j & 1) * (NSLOT * 8));

        if (rank == 0 && tid == 0) idxo[j] = f;  // scan emits farthest BEFORE update

        // distance update — IDENTICAL source expression to prior passing rounds
        const float2 cxy = sxy[f];
        const float cz = sz[f];
        const float cx = cxy.x, cy = cxy.y;
        float nd[PPT];
#pragma unroll
        for (int k = 0; k < PPT; k++) {
            float dx = X[k] - cx;
            float dy = Y[k] - cy;
            float dz = Z[k] - cz;
            float d = dx * dx + dy * dy + dz * dz;
            float v = fminf(D[k], d);
            D[k] = v;
            nd[k] = v;
        }

        // thread-level argmax tree over 8 values; prefer-left keeps lowest k
        // (k ascending == global index ascending): first-index tie-break.
        float bd[PPT]; int bk[PPT];
#pragma unroll
        for (int k = 0; k < PPT; k++) { bd[k] = nd[k]; bk[k] = k; }
#pragma unroll
        for (int s = PPT / 2; s > 0; s >>= 1) {
#pragma unroll
            for (int k = 0; k < PPT; k++) {
                if (k < s) {
                    if (bd[k + s] > bd[k]) { bd[k] = bd[k + s]; bk[k] = bk[k + s]; }
                }
            }
        }
        const float best = bd[0];
        const int   bi   = base + bk[0] * T;

        // warp-level: max dist bits, then max of (NN-1-idx) among maxima
        const u32 ub  = __float_as_uint(best);          // dist >= 0: bit order == float order
        const u32 wm  = __reduce_max_sync(0xFFFFFFFFu, ub);
        const u32 cnd = (ub == wm) ? (u32)(NN - 1 - bi) : 0u;
        const u32 wi  = __reduce_max_sync(0xFFFFFFFFu, cnd);

        // all-to-all: lanes 0..7 each fire ONE remote store (parallel fan-out)
        const u64 wkey = ((u64)wm << 32) | ((u64)tag << 16) | (u64)wi;
        if (lane < CSIZE)
            st_cluster64(peerAddr + bufOff, wkey);

        // every warp: CONVERGENT voted poll on all 64 slots (16B per lane)
        u64 k0, k1;
        do {
            vld64x2(pollAddr + bufOff, k0, k1);
        } while (__any_sync(0xFFFFFFFFu,
                 ((((u32)k0 >> 16) ^ tag) | (((u32)k1 >> 16) ^ tag)) != 0u));

        const u64 k  = (k1 > k0) ? k1 : k0;   // tags equal: dist, then first-index
        const u32 hi = (u32)(k >> 32);
        const u32 lo = (u32)k;
        const u32 M1 = __reduce_max_sync(0xFFFFFFFFu, hi);
        const u32 C1 = (hi == M1) ? lo : 0u;  // tag bits identical across lanes
        const u32 M2 = __reduce_max_sync(0xFFFFFFFFu, C1);
        f = NN - 1 - (int)(M2 & 0x3FFFu);
    }
}

// ---------------------------------------------------------------------------
// Gather feats: out[b][c][m] = feats[b][c][ idx[b][m] ]
// ---------------------------------------------------------------------------
extern "C" __global__ void gather_feats_kernel(const float* __restrict__ feats,
                                               float* __restrict__ out) {
    long long l = (long long)blockIdx.x * blockDim.x + threadIdx.x;
    const long long total = (long long)BB * CC * NPOINT;
    if (l >= total) return;
    int m = (int)(l % NPOINT);
    long long bc = l / NPOINT;          // b*C + c
    int b = (int)(bc / CC);
    int i = g_idx[b * NPOINT + m];
    out[l] = feats[bc * NN + i];
}

// ---------------------------------------------------------------------------
// Gather xyz: out[b][m][d] = xyz[b][idx[b][m]][d]
// ---------------------------------------------------------------------------
extern "C" __global__ void gather_xyz_kernel(const float* __restrict__ xyz,
                                             float* __restrict__ out) {
    int l = blockIdx.x * blockDim.x + threadIdx.x;   // over B*NPOINT
    if (l >= BB * NPOINT) return;
    int b = l / NPOINT;
    int i = g_idx[l];
    const float* src = xyz + ((size_t)b * NN + i) * 3;
    float* dst = out + (size_t)l * 3;
    dst[0] = src[0];
    dst[1] = src[1];
    dst[2] = src[2];
}

// ---------------------------------------------------------------------------
extern "C" void kernel_launch(void* const* d_in, const int* in_sizes, int n_in,
                              void* d_out, int out_size) {
    // Identify inputs by element count (robust to ordering):
    // feats = 8*128*16384 = 16777216, xyz = 8*16384*3 = 393216
    const float* feats = (const float*)d_in[0];
    const float* xyz   = (const float*)d_in[1];
    if (in_sizes[0] == BB * NN * 3) {
        xyz   = (const float*)d_in[0];
        feats = (const float*)d_in[1];
    }

    float* out = (float*)d_out;
    float* out_feats = out;                                   // B*C*NPOINT
    float* out_xyz   = out + (size_t)BB * CC * NPOINT;        // B*NPOINT*3

    const size_t smem = (size_t)3 * NN * sizeof(float)
                      + 2 * NSLOT * sizeof(u64);
    cudaFuncSetAttribute(fps_kernel,
                         cudaFuncAttributeMaxDynamicSharedMemorySize,
                         (int)smem);

    fps_kernel<<<BB * CSIZE, T, smem>>>(xyz);

    const long long feat_total = (long long)BB * CC * NPOINT;
    int gb = (int)((feat_total + 255) / 256);
    gather_feats_kernel<<<gb, 256>>>(feats, out_feats);

    int xb = (BB * NPOINT + 255) / 256;
    gather_xyz_kernel<<<xb, 256>>>(xyz, out_xyz);
}

// round 10
// speedup vs baseline: 3.8079x; 1.0850x over previous
#include <cuda_runtime.h>
#include <cstdint>

// Problem constants (fixed by the reference: B=8, N=16384, RATIO=0.5, C=128)
#define BB 8
#define NN 16384
#define NPOINT 8192
#define CC 128
#define T 128                // threads per CTA (4 warps) — R10: halve comm volume
#define CSIZE 8              // CTAs per batch — 16 regressed 3.5x (R7)
#define NC (NN / CSIZE)      // 2048 points per CTA
#define NWARP (T / 32)       // 4 warps
#define PPT (NC / T)         // 16 points per thread
#define NSLOT (CSIZE * NWARP)  // 32 cross slots per buffer (one per lane!)

typedef unsigned long long u64;
typedef unsigned int u32;

// Scratch: selected indices per batch (device global — no allocation allowed)
__device__ int g_idx[BB * NPOINT];

// ---------------------------------------------------------------------------
// helpers
// ---------------------------------------------------------------------------
__device__ __forceinline__ u32 smem_u32(const void* p) {
    return (u32)__cvta_generic_to_shared(p);
}
__device__ __forceinline__ u64 vld64(u32 a) {
    u64 v;
    asm volatile("ld.volatile.shared.b64 %0, [%1];" : "=l"(v) : "r"(a) : "memory");
    return v;
}
__device__ __forceinline__ u32 mapa_rank(u32 laddr, u32 rank) {
    u32 ra;
    asm volatile("mapa.shared::cluster.u32 %0, %1, %2;" : "=r"(ra) : "r"(laddr), "r"(rank));
    return ra;
}
__device__ __forceinline__ void st_cluster64(u32 raddr, u64 v) {
    asm volatile("st.relaxed.cluster.shared::cluster.b64 [%0], %1;" :: "r"(raddr), "l"(v) : "memory");
}

// ---------------------------------------------------------------------------
// FPS: 8-CTA cluster per batch, 128 threads/CTA (4 warps), 16 points/thread
// (register-resident). Per-SMSP compute issue identical to the 2704us kernel
// (points/CTA unchanged); comm volume halved: 32 slots, 32 remote stores,
// one-u64-per-lane poll.
//
// Per-point distance arithmetic is the VERBATIM scalar expression from the
// rel_err==0.0 kernels — do not touch (hand-reassociation flipped near-tie
// selections in R2).
//
// ONE-STAGE all-to-all reduction per iteration:
//   thread:  pairwise argmax tree over 16 points (prefer-left = lower index
//            on ties, exact jnp.argmax semantics)
//   warp:    2x REDUX -> warp key (held by EVERY lane)
//   all-to-all: lanes 0..7 each issue ONE remote store of the warp key to
//            rank=lane, slot [rank*NWARP+wid] (parallel fan-out)
//   every warp: CONVERGENT VOTED poll (divergent per-lane spin regressed 3x
//            in R8); lane L polls slot L (single vld64); 2x REDUX -> f.
// Keys: (dist_bits<<32) | (tag<<16) | (NN-1-idx); within one iteration all
// tags are equal so u64 max == (max dist, then first index) — jnp.argmax
// tie-breaking. Tags self-synchronize the spin; double buffering (j&1)
// prevents overwrite races: a warp writes buffer (j+2)&1 only after passing
// poll j+1, which required every warp of every rank to have posted j+1,
// which required them to have finished reading buffer j&1.
// ---------------------------------------------------------------------------
extern "C" __global__ void __launch_bounds__(T, 1) __cluster_dims__(CSIZE, 1, 1)
fps_kernel(const float* __restrict__ xyz)
{
    const int blk  = blockIdx.x;
    const int b    = blk / CSIZE;
    const u32 rank = (u32)(blk % CSIZE);
    const int tid  = threadIdx.x;
    const int wid  = tid >> 5;
    const int lane = tid & 31;

    extern __shared__ float smem[];
    float2* sxy = (float2*)smem;                    // [NN]  (128 KB)
    float*  sz  = smem + 2 * NN;                    // [NN]  (64 KB)
    u64* crossSlots = (u64*)(smem + 3 * NN);        // [2][NSLOT]

    const float* __restrict__ p = xyz + (size_t)b * NN * 3;

    // Full xyz table in smem (centroid lookup must cover all 16384 points)
    for (int i = tid; i < NN; i += T) {
        float x = p[3 * i + 0];
        float y = p[3 * i + 1];
        float z = p[3 * i + 2];
        sxy[i] = make_float2(x, y);
        sz[i]  = z;
    }
    if (tid < 2 * NSLOT) crossSlots[tid] = 0ull;
    __syncthreads();
    // all CTAs' slots must be zeroed before any peer's first DSMEM store
    asm volatile("barrier.cluster.arrive.aligned;" ::: "memory");
    asm volatile("barrier.cluster.wait.aligned;"   ::: "memory");

    // Own 16 points, register-resident: i_k = base + k*T (k asc => index asc)
    const int base = (int)rank * NC + tid;
    float X[PPT], Y[PPT], Z[PPT], D[PPT];
#pragma unroll
    for (int k = 0; k < PPT; k++) {
        const int i = base + k * T;
        float2 xy = sxy[i];
        X[k] = xy.x; Y[k] = xy.y; Z[k] = sz[i];
        D[k] = 1e10f;
    }

    const u32 csBase = smem_u32(crossSlots);

    // Per-lane peer address: lanes 0..7 target rank=lane, slot [rank*NWARP+wid].
    const u32 peerAddr = mapa_rank(csBase, (u32)(lane & (CSIZE - 1)))
                       + (u32)(((int)rank * NWARP + wid) * 8);

    // Lane L polls slot L (32 slots <-> 32 lanes).
    const u32 pollAddr = csBase + (u32)(lane * 8);

    int f = 0;   // init_far = 0 (reference)
    int* __restrict__ idxo = g_idx + b * NPOINT;

    for (int j = 0; j < NPOINT; j++) {
        const u32 tag = (u32)(j + 1);   // 1..8192 (14 bits)
        const u32 bufOff = (u32)((j & 1) * (NSLOT * 8));

        if (rank == 0 && tid == 0) idxo[j] = f;  // scan emits farthest BEFORE update

        // distance update — IDENTICAL source expression to prior passing rounds
        const float2 cxy = sxy[f];
        const float cz = sz[f];
        const float cx = cxy.x, cy = cxy.y;
        float nd[PPT];
#pragma unroll
        for (int k = 0; k < PPT; k++) {
            float dx = X[k] - cx;
            float dy = Y[k] - cy;
            float dz = Z[k] - cz;
            float d = dx * dx + dy * dy + dz * dz;
            float v = fminf(D[k], d);
            D[k] = v;
            nd[k] = v;
        }

        // thread-level argmax tree over 16 values; prefer-left keeps lowest k
        // (k ascending == global index ascending): first-index tie-break.
        float bd[PPT]; int bk[PPT];
#pragma unroll
        for (int k = 0; k < PPT; k++) { bd[k] = nd[k]; bk[k] = k; }
#pragma unroll
        for (int s = PPT / 2; s > 0; s >>= 1) {
#pragma unroll
            for (int k = 0; k < PPT; k++) {
                if (k < s) {
                    if (bd[k + s] > bd[k]) { bd[k] = bd[k + s]; bk[k] = bk[k + s]; }
                }
            }
        }
        const float best = bd[0];
        const int   bi   = base + bk[0] * T;

        // warp-level: max dist bits, then max of (NN-1-idx) among maxima
        const u32 ub  = __float_as_uint(best);          // dist >= 0: bit order == float order
        const u32 wm  = __reduce_max_sync(0xFFFFFFFFu, ub);
        const u32 cnd = (ub == wm) ? (u32)(NN - 1 - bi) : 0u;
        const u32 wi  = __reduce_max_sync(0xFFFFFFFFu, cnd);

        // all-to-all: lanes 0..7 each fire ONE remote store (parallel fan-out)
        const u64 wkey = ((u64)wm << 32) | ((u64)tag << 16) | (u64)wi;
        if (lane < CSIZE)
            st_cluster64(peerAddr + bufOff, wkey);

        // every warp: CONVERGENT voted poll, one slot per lane
        u64 k;
        do {
            k = vld64(pollAddr + bufOff);
        } while (__any_sync(0xFFFFFFFFu, (((u32)k >> 16) ^ tag) != 0u));

        const u32 hi = (u32)(k >> 32);
        const u32 lo = (u32)k;
        const u32 M1 = __reduce_max_sync(0xFFFFFFFFu, hi);
        const u32 C1 = (hi == M1) ? lo : 0u;  // tag bits identical across lanes
        const u32 M2 = __reduce_max_sync(0xFFFFFFFFu, C1);
        f = NN - 1 - (int)(M2 & 0x3FFFu);
    }
}

// ---------------------------------------------------------------------------
// Gather feats: out[b][c][m] = feats[b][c][ idx[b][m] ]
// ---------------------------------------------------------------------------
extern "C" __global__ void gather_feats_kernel(const float* __restrict__ feats,
                                               float* __restrict__ out) {
    long long l = (long long)blockIdx.x * blockDim.x + threadIdx.x;
    const long long total = (long long)BB * CC * NPOINT;
    if (l >= total) return;
    int m = (int)(l % NPOINT);
    long long bc = l / NPOINT;          // b*C + c
    int b = (int)(bc / CC);
    int i = g_idx[b * NPOINT + m];
    out[l] = feats[bc * NN + i];
}

// ---------------------------------------------------------------------------
// Gather xyz: out[b][m][d] = xyz[b][idx[b][m]][d]
// ---------------------------------------------------------------------------
extern "C" __global__ void gather_xyz_kernel(const float* __restrict__ xyz,
                                             float* __restrict__ out) {
    int l = blockIdx.x * blockDim.x + threadIdx.x;   // over B*NPOINT
    if (l >= BB * NPOINT) return;
    int b = l / NPOINT;
    int i = g_idx[l];
    const float* src = xyz + ((size_t)b * NN + i) * 3;
    float* dst = out + (size_t)l * 3;
    dst[0] = src[0];
    dst[1] = src[1];
    dst[2] = src[2];
}

// ---------------------------------------------------------------------------
extern "C" void kernel_launch(void* const* d_in, const int* in_sizes, int n_in,
                              void* d_out, int out_size) {
    // Identify inputs by element count (robust to ordering):
    // feats = 8*128*16384 = 16777216, xyz = 8*16384*3 = 393216
    const float* feats = (const float*)d_in[0];
    const float* xyz   = (const float*)d_in[1];
    if (in_sizes[0] == BB * NN * 3) {
        xyz   = (const float*)d_in[0];
        feats = (const float*)d_in[1];
    }

    float* out = (float*)d_out;
    float* out_feats = out;                                   // B*C*NPOINT
    float* out_xyz   = out + (size_t)BB * CC * NPOINT;        // B*NPOINT*3

    const size_t smem = (size_t)3 * NN * sizeof(float)
                      + 2 * NSLOT * sizeof(u64);
    cudaFuncSetAttribute(fps_kernel,
                         cudaFuncAttributeMaxDynamicSharedMemorySize,
                         (int)smem);

    fps_kernel<<<BB * CSIZE, T, smem>>>(xyz);

    const long long feat_total = (long long)BB * CC * NPOINT;
    int gb = (int)((feat_total + 255) / 256);
    gather_feats_kernel<<<gb, 256>>>(feats, out_feats);

    int xb = (BB * NPOINT + 255) / 256;
    gather_xyz_kernel<<<xb, 256>>>(xyz, out_xyz);
}